// round 16
// baseline (speedup 1.0000x reference)
#include <cuda_runtime.h>
#include <cuda_fp16.h>

#define EMB_ELEMS (7424 * 128)
__device__ __half g_emb_h[EMB_ELEMS];     // fp16 embedding table (1.9 MB)

__global__ void cvt_emb_kernel(const float* __restrict__ emb, int n)
{
    int i = blockIdx.x * blockDim.x + threadIdx.x;
    if (i < n) g_emb_h[i] = __float2half(emb[i]);
}

// Packed 2-wide fp32 add (Blackwell f32x2 pipe; PTX-only).
__device__ __forceinline__ float2 fadd2(float2 a, float2 b)
{
    float2 d;
    asm("{\n\t.reg .b64 ra,rb,rd;\n\t"
        "mov.b64 ra,{%2,%3};\n\tmov.b64 rb,{%4,%5};\n\t"
        "add.rn.f32x2 rd, ra, rb;\n\t"
        "mov.b64 {%0,%1}, rd;\n\t}"
        : "=f"(d.x), "=f"(d.y)
        : "f"(a.x), "f"(a.y), "f"(b.x), "f"(b.y));
    return d;
}

__device__ __forceinline__ void mma16816(float* d,
                                         unsigned a0, unsigned a1, unsigned a2, unsigned a3,
                                         unsigned b0, unsigned b1)
{
    asm volatile(
        "mma.sync.aligned.m16n8k16.row.col.f32.f16.f16.f32 "
        "{%0,%1,%2,%3}, {%4,%5,%6,%7}, {%8,%9}, {%0,%1,%2,%3};"
        : "+f"(d[0]), "+f"(d[1]), "+f"(d[2]), "+f"(d[3])
        : "r"(a0), "r"(a1), "r"(a2), "r"(a3), "r"(b0), "r"(b1));
}

__device__ __forceinline__ unsigned packrelu(float x, float y)
{
    __half2 h = __floats2half2_rn(fmaxf(x, 0.f), fmaxf(y, 0.f));
    return *(const unsigned*)&h;
}

#define WPB 4
#define THREADS (WPB * 32)
#define TR 16            // rows per warp (one MMA tile)
#define HT_STRIDE 68     // uints per h-tile row (64 data + 4 pad)

__global__ __launch_bounds__(THREADS, 7)   // <=73 regs -> 7 blocks/SM = 28 warps
void silk_nnue_fused(const int*   __restrict__ x,
                     const float* __restrict__ W2,
                     const float* __restrict__ b2,
                     const float* __restrict__ W3,
                     const float* __restrict__ b3,
                     const float* __restrict__ W4,
                     float*       __restrict__ out,
                     int nrows)
{
    // B-fragment-packed weights (validated R13-R15): stride 36 -> conflict-free.
    __shared__ unsigned sW2p[64 * 36];
    __shared__ unsigned sW3p[32 * 36];
    __shared__ float    sb2[32], sb3[32], sW4[64];
    __shared__ unsigned sht[WPB][TR * HT_STRIDE];   // per-warp fp16 h tile

    const int tid  = threadIdx.x;
    const int lane = tid & 31;
    const int w    = tid >> 5;

    for (int i = tid; i < 64 * 32; i += THREADS) {
        int kp = i >> 5, n = i & 31;
        __half2 p = __floats2half2_rn(W2[n * 128 + 2 * kp], W2[n * 128 + 2 * kp + 1]);
        sW2p[kp * 36 + n] = *(const unsigned*)&p;
    }
    for (int i = tid; i < 32 * 32; i += THREADS) {
        int kp = i >> 5, n = i & 31;
        __half2 p = __floats2half2_rn(W3[n * 64 + 2 * kp], W3[n * 64 + 2 * kp + 1]);
        sW3p[kp * 36 + n] = *(const unsigned*)&p;
    }
    if (tid < 32)      sb2[tid]      = b2[tid];
    else if (tid < 64) sb3[tid - 32] = b3[tid - 32];
    if (tid >= 64 && tid < 128) sW4[tid - 64] = W4[tid - 64];
    __syncthreads();

    const int gwarp = blockIdx.x * WPB + w;
    const int row0  = gwarp * TR;
    if (row0 >= nrows) return;
    const bool full = (row0 + TR <= nrows);

    unsigned* ht = sht[w];
    const uint4* __restrict__ embq = (const uint4*)g_emb_h;  // 16 uint4 per table row
    const int half   = lane >> 4;         // 0: row A of pair, 1: row B
    const int hlane  = lane & 15;
    const int hshift = half << 4;         // 0 or 16: extract my half's index

    // ---- Gather: half-warp LDG.128 (2 rows/instruction), ONE shuffle per load
    //      via 16-bit index-pair packing (idx < 7424 < 2^16).
    #pragma unroll
    for (int pass = 0; pass < 2; ++pass) {
        const int base = row0 + pass * 8;

        int xp[4];   // lane l holds slot l of all 8 rows; pack row-pairs locally
        #pragma unroll
        for (int p = 0; p < 4; ++p) {
            int rA = base + 2 * p, rB = base + 2 * p + 1;
            int iA = (full || rA < nrows) ? x[rA * 32 + lane] : 0;
            int iB = (full || rB < nrows) ? x[rB * 32 + lane] : 0;
            xp[p] = (iA & 0xffff) | (iB << 16);
        }

        float2 acc[4][4];    // [pair][4 half2-slots]
        #pragma unroll
        for (int p = 0; p < 4; ++p)
            #pragma unroll
            for (int s = 0; s < 4; ++s) acc[p][s] = make_float2(0.f, 0.f);

        for (int j = 0; j < 29; ++j) {
            #pragma unroll
            for (int p = 0; p < 4; ++p) {
                int both = __shfl_sync(0xffffffffu, xp[p], j);     // 1 SHFL, 2 rows
                int idx  = (both >> hshift) & 0xffff;
                uint4 v = __ldg(embq + (size_t)idx * 16 + hlane);  // LDG.128
                acc[p][0] = fadd2(acc[p][0], __half22float2(*(const __half2*)&v.x));
                acc[p][1] = fadd2(acc[p][1], __half22float2(*(const __half2*)&v.y));
                acc[p][2] = fadd2(acc[p][2], __half22float2(*(const __half2*)&v.z));
                acc[p][3] = fadd2(acc[p][3], __half22float2(*(const __half2*)&v.w));
            }
        }

        // ReLU + fp16 pack -> one STS.128 per pair (2 rows per instruction).
        #pragma unroll
        for (int p = 0; p < 4; ++p) {
            uint4 pk;
            __half2 e0 = __floats2half2_rn(fmaxf(acc[p][0].x, 0.f), fmaxf(acc[p][0].y, 0.f));
            __half2 e1 = __floats2half2_rn(fmaxf(acc[p][1].x, 0.f), fmaxf(acc[p][1].y, 0.f));
            __half2 e2 = __floats2half2_rn(fmaxf(acc[p][2].x, 0.f), fmaxf(acc[p][2].y, 0.f));
            __half2 e3 = __floats2half2_rn(fmaxf(acc[p][3].x, 0.f), fmaxf(acc[p][3].y, 0.f));
            pk.x = *(const unsigned*)&e0;  pk.y = *(const unsigned*)&e1;
            pk.z = *(const unsigned*)&e2;  pk.w = *(const unsigned*)&e3;
            int row = pass * 8 + 2 * p + half;
            *(uint4*)(ht + row * HT_STRIDE + 4 * hlane) = pk;
        }
    }
    __syncwarp();

    const int g  = lane >> 2;   // 0-7
    const int t4 = lane & 3;

    // ---- Layer 2: D2[16x32] = h[16x128] @ W2^T + b2 ----
    float d2[4][4];
    #pragma unroll
    for (int nt = 0; nt < 4; ++nt) {
        float bb0 = sb2[nt * 8 + 2 * t4];
        float bb1 = sb2[nt * 8 + 2 * t4 + 1];
        d2[nt][0] = bb0; d2[nt][1] = bb1; d2[nt][2] = bb0; d2[nt][3] = bb1;
    }
    #pragma unroll
    for (int kt = 0; kt < 8; ++kt) {
        unsigned a0 = ht[g * HT_STRIDE + kt * 8 + t4];
        unsigned a1 = ht[(g + 8) * HT_STRIDE + kt * 8 + t4];
        unsigned a2 = ht[g * HT_STRIDE + kt * 8 + 4 + t4];
        unsigned a3 = ht[(g + 8) * HT_STRIDE + kt * 8 + 4 + t4];
        #pragma unroll
        for (int nt = 0; nt < 4; ++nt) {
            unsigned b0 = sW2p[(kt * 8 + t4) * 36 + nt * 8 + g];
            unsigned b1 = sW2p[(kt * 8 + 4 + t4) * 36 + nt * 8 + g];
            mma16816(d2[nt], a0, a1, a2, a3, b0, b1);
        }
    }

    // ---- CReLU -> layer-3 A fragments (pure register transform) ----
    unsigned a3f[4][4];
    #pragma unroll
    for (int kk = 0; kk < 2; ++kk) {
        float s = kk ? -1.f : 1.f;
        #pragma unroll
        for (int p = 0; p < 2; ++p) {
            int kt  = kk * 2 + p;
            int ntA = p * 2, ntB = p * 2 + 1;
            a3f[kt][0] = packrelu(s * d2[ntA][0], s * d2[ntA][1]);
            a3f[kt][1] = packrelu(s * d2[ntA][2], s * d2[ntA][3]);
            a3f[kt][2] = packrelu(s * d2[ntB][0], s * d2[ntB][1]);
            a3f[kt][3] = packrelu(s * d2[ntB][2], s * d2[ntB][3]);
        }
    }

    // ---- Layer 3: D3[16x32] = a[16x64] @ W3^T + b3 ----
    float d3[4][4];
    #pragma unroll
    for (int nt = 0; nt < 4; ++nt) {
        float bb0 = sb3[nt * 8 + 2 * t4];
        float bb1 = sb3[nt * 8 + 2 * t4 + 1];
        d3[nt][0] = bb0; d3[nt][1] = bb1; d3[nt][2] = bb0; d3[nt][3] = bb1;
    }
    #pragma unroll
    for (int kt = 0; kt < 4; ++kt) {
        #pragma unroll
        for (int nt = 0; nt < 4; ++nt) {
            unsigned b0 = sW3p[(kt * 8 + t4) * 36 + nt * 8 + g];
            unsigned b1 = sW3p[(kt * 8 + 4 + t4) * 36 + nt * 8 + g];
            mma16816(d3[nt], a3f[kt][0], a3f[kt][1], a3f[kt][2], a3f[kt][3], b0, b1);
        }
    }

    // ---- Layer 4 + cross-lane reduction ----
    float p0 = 0.f, p1 = 0.f;
    #pragma unroll
    for (int nt = 0; nt < 4; ++nt) {
        #pragma unroll
        for (int j = 0; j < 2; ++j) {
            int n = nt * 8 + 2 * t4 + j;
            float wlo = sW4[n], whi = sW4[n + 32];
            float v0 = d3[nt][j];
            float v1 = d3[nt][2 + j];
            p0 += wlo * fmaxf(v0, 0.f) + whi * fmaxf(-v0, 0.f);
            p1 += wlo * fmaxf(v1, 0.f) + whi * fmaxf(-v1, 0.f);
        }
    }
    p0 += __shfl_xor_sync(0xffffffffu, p0, 1);
    p0 += __shfl_xor_sync(0xffffffffu, p0, 2);
    p1 += __shfl_xor_sync(0xffffffffu, p1, 1);
    p1 += __shfl_xor_sync(0xffffffffu, p1, 2);

    if (t4 == 0) {
        int r0i = row0 + g, r1i = row0 + 8 + g;
        if (r0i < nrows) out[r0i] = p0;
        if (r1i < nrows) out[r1i] = p1;
    }
}

extern "C" void kernel_launch(void* const* d_in, const int* in_sizes, int n_in,
                              void* d_out, int out_size)
{
    const int*   x   = (const int*)  d_in[0];
    const float* emb = (const float*)d_in[1];
    const float* W2  = (const float*)d_in[2];
    const float* b2  = (const float*)d_in[3];
    const float* W3  = (const float*)d_in[4];
    const float* b3  = (const float*)d_in[5];
    const float* W4  = (const float*)d_in[6];
    float* out = (float*)d_out;

    int nemb  = in_sizes[1];
    int nrows = in_sizes[0] / 32;

    cvt_emb_kernel<<<(nemb + 511) / 512, 512>>>(emb, nemb);

    int ntiles  = (nrows + TR - 1) / TR;
    int nblocks = (ntiles + WPB - 1) / WPB;
    silk_nnue_fused<<<nblocks, THREADS>>>(x, W2, b2, W3, b3, W4, out, nrows);
}

// round 17
// speedup vs baseline: 1.0233x; 1.0233x over previous
#include <cuda_runtime.h>
#include <cuda_fp16.h>

#define EMB_ELEMS (7424 * 128)
__device__ __half g_emb_h[EMB_ELEMS];     // fp16 embedding table (1.9 MB)

__global__ void cvt_emb_kernel(const float* __restrict__ emb, int n)
{
    int i = blockIdx.x * blockDim.x + threadIdx.x;
    if (i < n) g_emb_h[i] = __float2half(emb[i]);
}

// Packed 2-wide fp32 add (Blackwell f32x2 pipe; PTX-only).
__device__ __forceinline__ float2 fadd2(float2 a, float2 b)
{
    float2 d;
    asm("{\n\t.reg .b64 ra,rb,rd;\n\t"
        "mov.b64 ra,{%2,%3};\n\tmov.b64 rb,{%4,%5};\n\t"
        "add.rn.f32x2 rd, ra, rb;\n\t"
        "mov.b64 {%0,%1}, rd;\n\t}"
        : "=f"(d.x), "=f"(d.y)
        : "f"(a.x), "f"(a.y), "f"(b.x), "f"(b.y));
    return d;
}

__device__ __forceinline__ void mma16816(float* d,
                                         unsigned a0, unsigned a1, unsigned a2, unsigned a3,
                                         unsigned b0, unsigned b1)
{
    asm volatile(
        "mma.sync.aligned.m16n8k16.row.col.f32.f16.f16.f32 "
        "{%0,%1,%2,%3}, {%4,%5,%6,%7}, {%8,%9}, {%0,%1,%2,%3};"
        : "+f"(d[0]), "+f"(d[1]), "+f"(d[2]), "+f"(d[3])
        : "r"(a0), "r"(a1), "r"(a2), "r"(a3), "r"(b0), "r"(b1));
}

__device__ __forceinline__ unsigned packrelu(float x, float y)
{
    __half2 h = __floats2half2_rn(fmaxf(x, 0.f), fmaxf(y, 0.f));
    return *(const unsigned*)&h;
}

#define WPB 4
#define THREADS (WPB * 32)
#define TR 16            // rows per warp (one MMA tile)
#define HT_STRIDE 68     // uints per h-tile row (64 data + 4 pad)

__global__ __launch_bounds__(THREADS)
void silk_nnue_fused(const int*   __restrict__ x,
                     const float* __restrict__ W2,
                     const float* __restrict__ b2,
                     const float* __restrict__ W3,
                     const float* __restrict__ b3,
                     const float* __restrict__ W4,
                     float*       __restrict__ out,
                     int nrows)
{
    // B-fragment-packed weights (validated R13-R16): stride 36 -> conflict-free.
    __shared__ unsigned sW2p[64 * 36];
    __shared__ unsigned sW3p[32 * 36];
    __shared__ float    sb2[32], sb3[32], sW4[64];
    __shared__ unsigned sht[WPB][TR * HT_STRIDE];   // per-warp fp16 h tile

    const int tid  = threadIdx.x;
    const int lane = tid & 31;
    const int w    = tid >> 5;

    for (int i = tid; i < 64 * 32; i += THREADS) {
        int kp = i >> 5, n = i & 31;
        __half2 p = __floats2half2_rn(W2[n * 128 + 2 * kp], W2[n * 128 + 2 * kp + 1]);
        sW2p[kp * 36 + n] = *(const unsigned*)&p;
    }
    for (int i = tid; i < 32 * 32; i += THREADS) {
        int kp = i >> 5, n = i & 31;
        __half2 p = __floats2half2_rn(W3[n * 64 + 2 * kp], W3[n * 64 + 2 * kp + 1]);
        sW3p[kp * 36 + n] = *(const unsigned*)&p;
    }
    if (tid < 32)      sb2[tid]      = b2[tid];
    else if (tid < 64) sb3[tid - 32] = b3[tid - 32];
    if (tid >= 64 && tid < 128) sW4[tid - 64] = W4[tid - 64];
    __syncthreads();

    const int gwarp = blockIdx.x * WPB + w;
    const int row0  = gwarp * TR;
    if (row0 >= nrows) return;
    const bool full = (row0 + TR <= nrows);

    unsigned* ht = sht[w];
    const uint4* __restrict__ embq = (const uint4*)g_emb_h;  // 16 uint4 per table row
    const int half  = lane >> 4;          // 0: row A of pair, 1: row B
    const int hlane = lane & 15;          // position within half-warp

    // ---- Gather: half-warp LDG.128 (2 rows per load instruction).
    //      __ldcg: bypass L1 allocation — table misses L1 ~90% anyway; avoid
    //      fill/eviction traffic through the L1 datapath.
    #pragma unroll
    for (int pass = 0; pass < 2; ++pass) {
        const int base = row0 + pass * 8;

        int xi[8];
        #pragma unroll
        for (int r = 0; r < 8; ++r) {
            int row = base + r;
            xi[r] = (full || row < nrows) ? x[row * 32 + lane] : 0;
        }

        float2 acc[4][4];    // [pair][4 half2-slots]
        #pragma unroll
        for (int p = 0; p < 4; ++p)
            #pragma unroll
            for (int s = 0; s < 4; ++s) acc[p][s] = make_float2(0.f, 0.f);

        for (int j = 0; j < 29; ++j) {
            #pragma unroll
            for (int p = 0; p < 4; ++p) {
                int iA = __shfl_sync(0xffffffffu, xi[2 * p],     j);
                int iB = __shfl_sync(0xffffffffu, xi[2 * p + 1], j);
                int idx = half ? iB : iA;
                uint4 v = __ldcg(embq + (size_t)idx * 16 + hlane);  // LDG.128.CG
                acc[p][0] = fadd2(acc[p][0], __half22float2(*(const __half2*)&v.x));
                acc[p][1] = fadd2(acc[p][1], __half22float2(*(const __half2*)&v.y));
                acc[p][2] = fadd2(acc[p][2], __half22float2(*(const __half2*)&v.z));
                acc[p][3] = fadd2(acc[p][3], __half22float2(*(const __half2*)&v.w));
            }
        }

        // ReLU + fp16 pack -> one STS.128 per pair (2 rows per instruction).
        #pragma unroll
        for (int p = 0; p < 4; ++p) {
            uint4 pk;
            __half2 e0 = __floats2half2_rn(fmaxf(acc[p][0].x, 0.f), fmaxf(acc[p][0].y, 0.f));
            __half2 e1 = __floats2half2_rn(fmaxf(acc[p][1].x, 0.f), fmaxf(acc[p][1].y, 0.f));
            __half2 e2 = __floats2half2_rn(fmaxf(acc[p][2].x, 0.f), fmaxf(acc[p][2].y, 0.f));
            __half2 e3 = __floats2half2_rn(fmaxf(acc[p][3].x, 0.f), fmaxf(acc[p][3].y, 0.f));
            pk.x = *(const unsigned*)&e0;  pk.y = *(const unsigned*)&e1;
            pk.z = *(const unsigned*)&e2;  pk.w = *(const unsigned*)&e3;
            int row = pass * 8 + 2 * p + half;
            *(uint4*)(ht + row * HT_STRIDE + 4 * hlane) = pk;
        }
    }
    __syncwarp();

    const int g  = lane >> 2;   // 0-7
    const int t4 = lane & 3;

    // ---- Layer 2: D2[16x32] = h[16x128] @ W2^T + b2 ----
    float d2[4][4];
    #pragma unroll
    for (int nt = 0; nt < 4; ++nt) {
        float bb0 = sb2[nt * 8 + 2 * t4];
        float bb1 = sb2[nt * 8 + 2 * t4 + 1];
        d2[nt][0] = bb0; d2[nt][1] = bb1; d2[nt][2] = bb0; d2[nt][3] = bb1;
    }
    #pragma unroll
    for (int kt = 0; kt < 8; ++kt) {
        unsigned a0 = ht[g * HT_STRIDE + kt * 8 + t4];
        unsigned a1 = ht[(g + 8) * HT_STRIDE + kt * 8 + t4];
        unsigned a2 = ht[g * HT_STRIDE + kt * 8 + 4 + t4];
        unsigned a3 = ht[(g + 8) * HT_STRIDE + kt * 8 + 4 + t4];
        #pragma unroll
        for (int nt = 0; nt < 4; ++nt) {
            unsigned b0 = sW2p[(kt * 8 + t4) * 36 + nt * 8 + g];
            unsigned b1 = sW2p[(kt * 8 + 4 + t4) * 36 + nt * 8 + g];
            mma16816(d2[nt], a0, a1, a2, a3, b0, b1);
        }
    }

    // ---- CReLU -> layer-3 A fragments (pure register transform) ----
    unsigned a3f[4][4];
    #pragma unroll
    for (int kk = 0; kk < 2; ++kk) {
        float s = kk ? -1.f : 1.f;
        #pragma unroll
        for (int p = 0; p < 2; ++p) {
            int kt  = kk * 2 + p;
            int ntA = p * 2, ntB = p * 2 + 1;
            a3f[kt][0] = packrelu(s * d2[ntA][0], s * d2[ntA][1]);
            a3f[kt][1] = packrelu(s * d2[ntA][2], s * d2[ntA][3]);
            a3f[kt][2] = packrelu(s * d2[ntB][0], s * d2[ntB][1]);
            a3f[kt][3] = packrelu(s * d2[ntB][2], s * d2[ntB][3]);
        }
    }

    // ---- Layer 3: D3[16x32] = a[16x64] @ W3^T + b3 ----
    float d3[4][4];
    #pragma unroll
    for (int nt = 0; nt < 4; ++nt) {
        float bb0 = sb3[nt * 8 + 2 * t4];
        float bb1 = sb3[nt * 8 + 2 * t4 + 1];
        d3[nt][0] = bb0; d3[nt][1] = bb1; d3[nt][2] = bb0; d3[nt][3] = bb1;
    }
    #pragma unroll
    for (int kt = 0; kt < 4; ++kt) {
        #pragma unroll
        for (int nt = 0; nt < 4; ++nt) {
            unsigned b0 = sW3p[(kt * 8 + t4) * 36 + nt * 8 + g];
            unsigned b1 = sW3p[(kt * 8 + 4 + t4) * 36 + nt * 8 + g];
            mma16816(d3[nt], a3f[kt][0], a3f[kt][1], a3f[kt][2], a3f[kt][3], b0, b1);
        }
    }

    // ---- Layer 4 + cross-lane reduction ----
    float p0 = 0.f, p1 = 0.f;
    #pragma unroll
    for (int nt = 0; nt < 4; ++nt) {
        #pragma unroll
        for (int j = 0; j < 2; ++j) {
            int n = nt * 8 + 2 * t4 + j;
            float wlo = sW4[n], whi = sW4[n + 32];
            float v0 = d3[nt][j];
            float v1 = d3[nt][2 + j];
            p0 += wlo * fmaxf(v0, 0.f) + whi * fmaxf(-v0, 0.f);
            p1 += wlo * fmaxf(v1, 0.f) + whi * fmaxf(-v1, 0.f);
        }
    }
    p0 += __shfl_xor_sync(0xffffffffu, p0, 1);
    p0 += __shfl_xor_sync(0xffffffffu, p0, 2);
    p1 += __shfl_xor_sync(0xffffffffu, p1, 1);
    p1 += __shfl_xor_sync(0xffffffffu, p1, 2);

    if (t4 == 0) {
        int r0i = row0 + g, r1i = row0 + 8 + g;
        if (r0i < nrows) out[r0i] = p0;
        if (r1i < nrows) out[r1i] = p1;
    }
}

extern "C" void kernel_launch(void* const* d_in, const int* in_sizes, int n_in,
                              void* d_out, int out_size)
{
    const int*   x   = (const int*)  d_in[0];
    const float* emb = (const float*)d_in[1];
    const float* W2  = (const float*)d_in[2];
    const float* b2  = (const float*)d_in[3];
    const float* W3  = (const float*)d_in[4];
    const float* b3  = (const float*)d_in[5];
    const float* W4  = (const float*)d_in[6];
    float* out = (float*)d_out;

    int nemb  = in_sizes[1];
    int nrows = in_sizes[0] / 32;

    cvt_emb_kernel<<<(nemb + 511) / 512, 512>>>(emb, nemb);

    int ntiles  = (nrows + TR - 1) / TR;
    int nblocks = (ntiles + WPB - 1) / WPB;
    silk_nnue_fused<<<nblocks, THREADS>>>(x, W2, b2, W3, b3, W4, out, nrows);
}